// round 14
// baseline (speedup 1.0000x reference)
#include <cuda_runtime.h>
#include <cuda_fp16.h>
#include <cstdint>

typedef uint32_t u32;

#define NPOS    (4096*128)
#define TILE    256
#define NTILES  (NPOS/TILE)    // 2048
#define THREADS 256
#define NBLOCKS 444

#define RSTRIDE  72            // halves per row, W2/W3 tiles (conflict-free ldmatrix)
#define W1STRIDE 40            // halves per row, W1 tile

// ---- dynamic SMEM layout (bytes) ----
#define SM_C1   0              // 64 f   (256)
#define SM_C2   256            // 64 f   (256)
#define SM_C3   512            // 128 f  (512)
#define SM_W1B  1024           // 64 ch x 40 halves (5120)
#define SM_W2   6144           // 64  x 72 halves   (9216)
#define SM_W3   15360          // 128 x 72 halves   (18432)
#define SMEM_TOTAL 33792

static __device__ __forceinline__ u32 sptr(const void* p) {
    u32 a;
    asm("{ .reg .u64 t; cvta.to.shared.u64 t, %1; cvt.u32.u64 %0, t; }" : "=r"(a) : "l"(p));
    return a;
}
static __device__ __forceinline__ void ldm4(u32& r0, u32& r1, u32& r2, u32& r3, u32 addr) {
    asm volatile("ldmatrix.sync.aligned.m8n8.x4.shared.b16 {%0,%1,%2,%3}, [%4];"
                 : "=r"(r0), "=r"(r1), "=r"(r2), "=r"(r3) : "r"(addr));
}
static __device__ __forceinline__ void mma16816(float c[4], const u32 a[4], u32 b0, u32 b1) {
    asm volatile("mma.sync.aligned.m16n8k16.row.col.f32.f16.f16.f32 "
                 "{%0,%1,%2,%3}, {%4,%5,%6,%7}, {%8,%9}, {%0,%1,%2,%3};"
                 : "+f"(c[0]), "+f"(c[1]), "+f"(c[2]), "+f"(c[3])
                 : "r"(a[0]), "r"(a[1]), "r"(a[2]), "r"(a[3]), "r"(b0), "r"(b1));
}
static __device__ __forceinline__ u32 pack2(float a, float b) {
    __half2 h = __floats2half2_rn(a, b);
    return *reinterpret_cast<u32*>(&h);
}

extern "C" __global__ void __launch_bounds__(THREADS, 3)
pn_mma_kernel(const float* __restrict__ pc,  const float* __restrict__ valid,
              const float* __restrict__ W1,  const float* __restrict__ b1,
              const float* __restrict__ g1,  const float* __restrict__ be1,
              const float* __restrict__ m1,  const float* __restrict__ v1,
              const float* __restrict__ W2,  const float* __restrict__ b2,
              const float* __restrict__ g2,  const float* __restrict__ be2,
              const float* __restrict__ m2,  const float* __restrict__ v2,
              const float* __restrict__ W3,  const float* __restrict__ b3,
              const float* __restrict__ g3,  const float* __restrict__ be3,
              const float* __restrict__ m3,  const float* __restrict__ v3,
              float* __restrict__ out)
{
    extern __shared__ char smem[];
    const u32 sb = sptr(smem);
    const int t    = threadIdx.x;
    const int lane = t & 31;
    const int w    = t >> 5;

    float*  s_c1  = reinterpret_cast<float*>(smem + SM_C1);
    float*  s_c2  = reinterpret_cast<float*>(smem + SM_C2);
    float*  s_c3  = reinterpret_cast<float*>(smem + SM_C3);
    __half* s_w1b = reinterpret_cast<__half*>(smem + SM_W1B);
    __half* s_w2  = reinterpret_cast<__half*>(smem + SM_W2);
    __half* s_w3  = reinterpret_cast<__half*>(smem + SM_W3);

    // ---- one-time prep: fold BN, convert weights to fp16 ----
    if (t < 64) {
        float inv1 = g1[t] * rsqrtf(v1[t] + 1e-5f);
        s_c1[t] = be1[t] + (b1[t] - m1[t]) * inv1;
        float inv2 = g2[t] * rsqrtf(v2[t] + 1e-5f);
        s_c2[t] = be2[t] + (b2[t] - m2[t]) * inv2;
    }
    if (t < 128) {
        float inv3 = g3[t] * rsqrtf(v3[t] + 1e-5f);
        s_c3[t] = be3[t] + (b3[t] - m3[t]) * inv3;
    }
    // W1 folded, fp16, K-major padded to k16 (k>=3 zero)
    for (int i = t; i < 64*16; i += THREADS) {
        int ch = i >> 4, k = i & 15;
        float inv1 = g1[ch] * rsqrtf(v1[ch] + 1e-5f);
        float wv = (k < 3) ? W1[3*ch + k] * inv1 : 0.f;
        s_w1b[ch*W1STRIDE + k] = __float2half_rn(wv);
    }
    for (int i = t; i < 64*64; i += THREADS) {
        int n = i >> 6, k = i & 63;
        float inv2 = g2[n] * rsqrtf(v2[n] + 1e-5f);
        s_w2[n*RSTRIDE + k] = __float2half_rn(W2[i] * inv2);
    }
    for (int i = t; i < 128*64; i += THREADS) {
        int n = i >> 6, k = i & 63;
        float inv3 = g3[n] * rsqrtf(v3[n] + 1e-5f);
        s_w3[n*RSTRIDE + k] = __float2half_rn(W3[i] * inv3);
    }
    __syncthreads();   // weights/biases ready; NO further block syncs

    // ---- per-thread fragment geometry ----
    const int qr  = lane >> 2;            // fragment row in 8
    const int qc  = (lane & 3) * 2;       // fragment col pair
    const int kq  = lane & 3;             // k-pair selector for layer-1 A
    const int lr8 = (lane & 7) + ((lane >> 3) & 1) * 8;
    const int lc8 = (lane >> 4) * 8;

    const u32 w1base = sb + SM_W1B + (u32)(((lane & 15)*W1STRIDE + lc8)*2);
    const u32 w2base = sb + SM_W2  + (u32)(((lane & 15)*RSTRIDE + lc8)*2);
    const u32 w3base = sb + SM_W3  + (u32)((lr8*RSTRIDE + lc8)*2);

    const int oddq = lane & 1;
    const int colq = (oddq << 3) + (((lane >> 1) & 1) << 2);  // 0/4/8/12 in 16

    // ---- prefetch first tile (lane owns pos w*32+lane, i.e. pos t) ----
    int tile = blockIdx.x;
    float x0 = 0.f, x1 = 0.f, x2 = 0.f, vld = 0.f;
    if (tile < NTILES) {
        int px = tile*TILE + t;
        x0 = pc[px]; x1 = pc[NPOS + px]; x2 = pc[2*NPOS + px];
        vld = valid[px];
    }

    for (; tile < NTILES; tile += gridDim.x) {
        const int p0 = tile * TILE;

        // ---- snapshot current tile inputs, issue next-tile prefetch ----
        const u32 h01 = pack2(x0, x1);          // k-pair 0 of X row
        const u32 h2  = pack2(x2, 0.f);         // k-pair 1 (x2, pad)
        const float vldc = vld;
        {
            int ntile = tile + gridDim.x;
            x0 = x1 = x2 = vld = 0.f;
            if (ntile < NTILES) {
                int px = ntile*TILE + t;
                x0 = pc[px]; x1 = pc[NPOS + px]; x2 = pc[2*NPOS + px];
                vld = valid[px];
            }
        }

        // ---- build layer-1 A fragments via intra-warp shuffles ----
        u32 xa[2][4];                            // [pb][a0..a3]; a2=a3=0 (k>=8)
        #pragma unroll
        for (int pb = 0; pb < 2; ++pb) {
            int s0 = pb*16 + qr, s1 = s0 + 8;
            u32 p01a = __shfl_sync(0xffffffffu, h01, s0);
            u32 p2a  = __shfl_sync(0xffffffffu, h2,  s0);
            u32 p01b = __shfl_sync(0xffffffffu, h01, s1);
            u32 p2b  = __shfl_sync(0xffffffffu, h2,  s1);
            xa[pb][0] = (kq == 0) ? p01a : ((kq == 1) ? p2a : 0u);
            xa[pb][1] = (kq == 0) ? p01b : ((kq == 1) ? p2b : 0u);
            xa[pb][2] = 0u;
            xa[pb][3] = 0u;
        }

        // ---- layer 1 in two n-halves (acc1 live range halved; no recompute) ----
        u32 y1a[2][4][4];
        #pragma unroll
        for (int g = 0; g < 2; ++g) {
            float acc1[2][4][4];
            #pragma unroll
            for (int j = 0; j < 4; ++j) {
                float2 bb = *reinterpret_cast<const float2*>(&s_c1[(4*g + j)*8 + qc]);
                #pragma unroll
                for (int pb = 0; pb < 2; ++pb) {
                    acc1[pb][j][0] = bb.x; acc1[pb][j][1] = bb.y;
                    acc1[pb][j][2] = bb.x; acc1[pb][j][3] = bb.y;
                }
            }
            #pragma unroll
            for (int npl = 0; npl < 2; ++npl) {
                const int np = 2*g + npl;
                u32 b[4];
                ldm4(b[0], b[1], b[2], b[3], w1base + np*(16*W1STRIDE*2));
                mma16816(acc1[0][2*npl],   xa[0], b[0], b[2]);
                mma16816(acc1[0][2*npl+1], xa[0], b[1], b[3]);
                mma16816(acc1[1][2*npl],   xa[1], b[0], b[2]);
                mma16816(acc1[1][2*npl+1], xa[1], b[1], b[3]);
            }
            // pack this half -> y1a k-groups 2g, 2g+1
            #pragma unroll
            for (int jj = 0; jj < 2; ++jj) {
                const int kt = 2*g + jj;
                #pragma unroll
                for (int pb = 0; pb < 2; ++pb) {
                    y1a[pb][kt][0] = pack2(fmaxf(acc1[pb][2*jj][0],   0.f), fmaxf(acc1[pb][2*jj][1],   0.f));
                    y1a[pb][kt][1] = pack2(fmaxf(acc1[pb][2*jj][2],   0.f), fmaxf(acc1[pb][2*jj][3],   0.f));
                    y1a[pb][kt][2] = pack2(fmaxf(acc1[pb][2*jj+1][0], 0.f), fmaxf(acc1[pb][2*jj+1][1], 0.f));
                    y1a[pb][kt][3] = pack2(fmaxf(acc1[pb][2*jj+1][2], 0.f), fmaxf(acc1[pb][2*jj+1][3], 0.f));
                }
            }
        }

        // ---- layer 2 in two n-halves (acc2 live range halved; same ldm count) ----
        u32 y2b[2][4][2][2];
        #pragma unroll
        for (int g = 0; g < 2; ++g) {
            float acc2[2][4][4];
            #pragma unroll
            for (int j = 0; j < 4; ++j) {
                float2 bb = *reinterpret_cast<const float2*>(&s_c2[(4*g + j)*8 + qc]);
                #pragma unroll
                for (int pb = 0; pb < 2; ++pb) {
                    acc2[pb][j][0] = bb.x; acc2[pb][j][1] = bb.y;
                    acc2[pb][j][2] = bb.x; acc2[pb][j][3] = bb.y;
                }
            }
            #pragma unroll
            for (int kt = 0; kt < 4; ++kt) {
                #pragma unroll
                for (int npl = 0; npl < 2; ++npl) {
                    const int np = 2*g + npl;
                    u32 b[4];
                    ldm4(b[0], b[1], b[2], b[3], w2base + np*(16*RSTRIDE*2) + kt*32);
                    // x4 fill: b0=(nlo,klo) b1=(nhi,klo) b2=(nlo,khi) b3=(nhi,khi)
                    mma16816(acc2[0][2*npl],   y1a[0][kt], b[0], b[2]);
                    mma16816(acc2[0][2*npl+1], y1a[0][kt], b[1], b[3]);
                    mma16816(acc2[1][2*npl],   y1a[1][kt], b[0], b[2]);
                    mma16816(acc2[1][2*npl+1], y1a[1][kt], b[1], b[3]);
                }
            }
            // pack this half -> layer-3 B fragments, k-groups 2g, 2g+1
            #pragma unroll
            for (int jj = 0; jj < 2; ++jj) {
                const int kt = 2*g + jj;
                #pragma unroll
                for (int pb = 0; pb < 2; ++pb) {
                    y2b[pb][kt][0][0] = pack2(fmaxf(acc2[pb][2*jj][0],   0.f), fmaxf(acc2[pb][2*jj][1],   0.f));
                    y2b[pb][kt][0][1] = pack2(fmaxf(acc2[pb][2*jj+1][0], 0.f), fmaxf(acc2[pb][2*jj+1][1], 0.f));
                    y2b[pb][kt][1][0] = pack2(fmaxf(acc2[pb][2*jj][2],   0.f), fmaxf(acc2[pb][2*jj][3],   0.f));
                    y2b[pb][kt][1][1] = pack2(fmaxf(acc2[pb][2*jj+1][2], 0.f), fmaxf(acc2[pb][2*jj+1][3], 0.f));
                }
            }
        }

        // ---- valid mask for epilogue columns via shuffle ----
        float2 vv[2][2];
        #pragma unroll
        for (int pb = 0; pb < 2; ++pb)
            #pragma unroll
            for (int h = 0; h < 2; ++h) {
                int src = pb*16 + h*8 + qc;
                vv[pb][h].x = __shfl_sync(0xffffffffu, vldc, src);
                vv[pb][h].y = __shfl_sync(0xffffffffu, vldc, src + 1);
            }

        // ---- layer 3: [out3 128][pos 32] per warp, coalesced STG.128 ----
        {
            float* outb = out + (size_t)p0 + w*32;
            #pragma unroll
            for (int ob = 0; ob < 8; ++ob) {
                float bq0 = s_c3[ob*16 + qr];
                float bq8 = s_c3[ob*16 + qr + 8];
                float acc[2][2][4];
                #pragma unroll
                for (int pb = 0; pb < 2; ++pb)
                    #pragma unroll
                    for (int h = 0; h < 2; ++h) {
                        acc[pb][h][0] = bq0; acc[pb][h][1] = bq0;
                        acc[pb][h][2] = bq8; acc[pb][h][3] = bq8;
                    }
                #pragma unroll
                for (int kt = 0; kt < 4; ++kt) {
                    u32 a[4];
                    ldm4(a[0], a[1], a[2], a[3], w3base + ob*(16*RSTRIDE*2) + kt*32);
                    mma16816(acc[0][0], a, y2b[0][kt][0][0], y2b[0][kt][0][1]);
                    mma16816(acc[0][1], a, y2b[0][kt][1][0], y2b[0][kt][1][1]);
                    mma16816(acc[1][0], a, y2b[1][kt][0][0], y2b[1][kt][0][1]);
                    mma16816(acc[1][1], a, y2b[1][kt][1][0], y2b[1][kt][1][1]);
                }
                const int c0i = ob*16 + qr;
                #pragma unroll
                for (int pb = 0; pb < 2; ++pb) {
                    float r0 = fmaxf(acc[pb][0][0], 0.f) * vv[pb][0].x;
                    float r1 = fmaxf(acc[pb][0][1], 0.f) * vv[pb][0].y;
                    float r2 = fmaxf(acc[pb][0][2], 0.f) * vv[pb][0].x;
                    float r3 = fmaxf(acc[pb][0][3], 0.f) * vv[pb][0].y;
                    float s0 = fmaxf(acc[pb][1][0], 0.f) * vv[pb][1].x;
                    float s1 = fmaxf(acc[pb][1][1], 0.f) * vv[pb][1].y;
                    float s2 = fmaxf(acc[pb][1][2], 0.f) * vv[pb][1].x;
                    float s3 = fmaxf(acc[pb][1][3], 0.f) * vv[pb][1].y;
                    float m0 = oddq ? r0 : s0;
                    float m1 = oddq ? r1 : s1;
                    float m2 = oddq ? r2 : s2;
                    float m3 = oddq ? r3 : s3;
                    float g0  = __shfl_xor_sync(0xffffffffu, m0, 1);
                    float g1v = __shfl_xor_sync(0xffffffffu, m1, 1);
                    float g2v = __shfl_xor_sync(0xffffffffu, m2, 1);
                    float g3v = __shfl_xor_sync(0xffffffffu, m3, 1);
                    float4 t0, t1;
                    t0.x = oddq ? g0  : r0;  t0.y = oddq ? g1v : r1;
                    t0.z = oddq ? s0  : g0;  t0.w = oddq ? s1  : g1v;
                    t1.x = oddq ? g2v : r2;  t1.y = oddq ? g3v : r3;
                    t1.z = oddq ? s2  : g2v; t1.w = oddq ? s3  : g3v;
                    const int colb = pb*16 + colq;
                    *reinterpret_cast<float4*>(outb + (size_t)c0i*NPOS + colb)     = t0;
                    *reinterpret_cast<float4*>(outb + (size_t)(c0i+8)*NPOS + colb) = t1;
                }
            }
        }
    }
}

extern "C" void kernel_launch(void* const* d_in, const int* in_sizes, int n_in,
                              void* d_out, int out_size)
{
    (void)in_sizes; (void)n_in; (void)out_size;
    cudaFuncSetAttribute(pn_mma_kernel,
                         cudaFuncAttributeMaxDynamicSharedMemorySize, SMEM_TOTAL);
    pn_mma_kernel<<<NBLOCKS, THREADS, SMEM_TOTAL>>>(
        (const float*)d_in[0],  (const float*)d_in[1],
        (const float*)d_in[2],  (const float*)d_in[3],  (const float*)d_in[4],
        (const float*)d_in[5],  (const float*)d_in[6],  (const float*)d_in[7],
        (const float*)d_in[8],  (const float*)d_in[9],  (const float*)d_in[10],
        (const float*)d_in[11], (const float*)d_in[12], (const float*)d_in[13],
        (const float*)d_in[14], (const float*)d_in[15], (const float*)d_in[16],
        (const float*)d_in[17], (const float*)d_in[18], (const float*)d_in[19],
        (float*)d_out);
}

// round 15
// speedup vs baseline: 1.6049x; 1.6049x over previous
#include <cuda_runtime.h>
#include <cuda_fp16.h>
#include <cstdint>

typedef uint32_t u32;

#define NPOS    (4096*128)
#define TILE    256
#define NTILES  (NPOS/TILE)    // 2048
#define THREADS 256
#define NBLOCKS 296

#define RSTRIDE  72            // halves per row, W2/W3 tiles (conflict-free ldmatrix)
#define W1STRIDE 40            // halves per row, W1 tile

// ---- dynamic SMEM layout (bytes) ----
#define SM_C1   0              // 64 f   (256)
#define SM_C2   256            // 64 f   (256)
#define SM_C3   512            // 128 f  (512)
#define SM_W1B  1024           // 64 ch x 40 halves (5120)
#define SM_W2   6144           // 64  x 72 halves   (9216)
#define SM_W3   15360          // 128 x 72 halves   (18432)
#define SMEM_TOTAL 33792

static __device__ __forceinline__ u32 sptr(const void* p) {
    u32 a;
    asm("{ .reg .u64 t; cvta.to.shared.u64 t, %1; cvt.u32.u64 %0, t; }" : "=r"(a) : "l"(p));
    return a;
}
static __device__ __forceinline__ void ldm4(u32& r0, u32& r1, u32& r2, u32& r3, u32 addr) {
    asm volatile("ldmatrix.sync.aligned.m8n8.x4.shared.b16 {%0,%1,%2,%3}, [%4];"
                 : "=r"(r0), "=r"(r1), "=r"(r2), "=r"(r3) : "r"(addr));
}
static __device__ __forceinline__ void mma16816(float c[4], const u32 a[4], u32 b0, u32 b1) {
    asm volatile("mma.sync.aligned.m16n8k16.row.col.f32.f16.f16.f32 "
                 "{%0,%1,%2,%3}, {%4,%5,%6,%7}, {%8,%9}, {%0,%1,%2,%3};"
                 : "+f"(c[0]), "+f"(c[1]), "+f"(c[2]), "+f"(c[3])
                 : "r"(a[0]), "r"(a[1]), "r"(a[2]), "r"(a[3]), "r"(b0), "r"(b1));
}
static __device__ __forceinline__ u32 pack2(float a, float b) {
    __half2 h = __floats2half2_rn(a, b);
    return *reinterpret_cast<u32*>(&h);
}

extern "C" __global__ void __launch_bounds__(THREADS, 2)
pn_mma_kernel(const float* __restrict__ pc,  const float* __restrict__ valid,
              const float* __restrict__ W1,  const float* __restrict__ b1,
              const float* __restrict__ g1,  const float* __restrict__ be1,
              const float* __restrict__ m1,  const float* __restrict__ v1,
              const float* __restrict__ W2,  const float* __restrict__ b2,
              const float* __restrict__ g2,  const float* __restrict__ be2,
              const float* __restrict__ m2,  const float* __restrict__ v2,
              const float* __restrict__ W3,  const float* __restrict__ b3,
              const float* __restrict__ g3,  const float* __restrict__ be3,
              const float* __restrict__ m3,  const float* __restrict__ v3,
              float* __restrict__ out)
{
    extern __shared__ char smem[];
    const u32 sb = sptr(smem);
    const int t    = threadIdx.x;
    const int lane = t & 31;
    const int w    = t >> 5;

    float*  s_c1  = reinterpret_cast<float*>(smem + SM_C1);
    float*  s_c2  = reinterpret_cast<float*>(smem + SM_C2);
    float*  s_c3  = reinterpret_cast<float*>(smem + SM_C3);
    __half* s_w1b = reinterpret_cast<__half*>(smem + SM_W1B);
    __half* s_w2  = reinterpret_cast<__half*>(smem + SM_W2);
    __half* s_w3  = reinterpret_cast<__half*>(smem + SM_W3);

    // ---- one-time prep: fold BN, convert weights to fp16 ----
    if (t < 64) {
        float inv1 = g1[t] * rsqrtf(v1[t] + 1e-5f);
        s_c1[t] = be1[t] + (b1[t] - m1[t]) * inv1;
        float inv2 = g2[t] * rsqrtf(v2[t] + 1e-5f);
        s_c2[t] = be2[t] + (b2[t] - m2[t]) * inv2;
    }
    if (t < 128) {
        float inv3 = g3[t] * rsqrtf(v3[t] + 1e-5f);
        s_c3[t] = be3[t] + (b3[t] - m3[t]) * inv3;
    }
    // W1 folded, fp16, K-major padded to k16 (k>=3 zero)
    for (int i = t; i < 64*16; i += THREADS) {
        int ch = i >> 4, k = i & 15;
        float inv1 = g1[ch] * rsqrtf(v1[ch] + 1e-5f);
        float wv = (k < 3) ? W1[3*ch + k] * inv1 : 0.f;
        s_w1b[ch*W1STRIDE + k] = __float2half_rn(wv);
    }
    for (int i = t; i < 64*64; i += THREADS) {
        int n = i >> 6, k = i & 63;
        float inv2 = g2[n] * rsqrtf(v2[n] + 1e-5f);
        s_w2[n*RSTRIDE + k] = __float2half_rn(W2[i] * inv2);
    }
    for (int i = t; i < 128*64; i += THREADS) {
        int n = i >> 6, k = i & 63;
        float inv3 = g3[n] * rsqrtf(v3[n] + 1e-5f);
        s_w3[n*RSTRIDE + k] = __float2half_rn(W3[i] * inv3);
    }
    __syncthreads();   // weights/biases ready; NO further block syncs

    // ---- per-thread fragment geometry ----
    const int qr  = lane >> 2;            // fragment row in 8
    const int qc  = (lane & 3) * 2;       // fragment col pair
    const int kq  = lane & 3;             // k-pair selector for layer-1 A
    const int lr8 = (lane & 7) + ((lane >> 3) & 1) * 8;
    const int lc8 = (lane >> 4) * 8;

    const u32 w1base = sb + SM_W1B + (u32)(((lane & 15)*W1STRIDE + lc8)*2);
    const u32 w2base = sb + SM_W2  + (u32)(((lane & 15)*RSTRIDE + lc8)*2);
    const u32 w3base = sb + SM_W3  + (u32)((lr8*RSTRIDE + lc8)*2);

    const int oddq = lane & 1;
    const int colq = (oddq << 3) + (((lane >> 1) & 1) << 2);  // 0/4/8/12 in 16

    // ---- prefetch first tile (lane owns pos w*32+lane, i.e. pos t) ----
    int tile = blockIdx.x;
    float x0 = 0.f, x1 = 0.f, x2 = 0.f, vld = 0.f;
    if (tile < NTILES) {
        int px = tile*TILE + t;
        x0 = __ldcs(pc + px);
        x1 = __ldcs(pc + NPOS + px);
        x2 = __ldcs(pc + 2*NPOS + px);
        vld = __ldcs(valid + px);
    }

    for (; tile < NTILES; tile += gridDim.x) {
        const int p0 = tile * TILE;

        // ---- snapshot current tile inputs, issue next-tile prefetch ----
        const u32 h01 = pack2(x0, x1);          // k-pair 0 of X row
        const u32 h2  = pack2(x2, 0.f);         // k-pair 1 (x2, pad)
        const float vldc = vld;
        {
            int ntile = tile + gridDim.x;
            x0 = x1 = x2 = vld = 0.f;
            if (ntile < NTILES) {
                int px = ntile*TILE + t;
                x0 = __ldcs(pc + px);
                x1 = __ldcs(pc + NPOS + px);
                x2 = __ldcs(pc + 2*NPOS + px);
                vld = __ldcs(valid + px);
            }
        }

        // ---- build layer-1 A fragments via intra-warp shuffles ----
        u32 xa[2][4];                            // [pb][a0..a3]; a2=a3=0 (k>=8)
        #pragma unroll
        for (int pb = 0; pb < 2; ++pb) {
            int s0 = pb*16 + qr, s1 = s0 + 8;
            u32 p01a = __shfl_sync(0xffffffffu, h01, s0);
            u32 p2a  = __shfl_sync(0xffffffffu, h2,  s0);
            u32 p01b = __shfl_sync(0xffffffffu, h01, s1);
            u32 p2b  = __shfl_sync(0xffffffffu, h2,  s1);
            xa[pb][0] = (kq == 0) ? p01a : ((kq == 1) ? p2a : 0u);
            xa[pb][1] = (kq == 0) ? p01b : ((kq == 1) ? p2b : 0u);
            xa[pb][2] = 0u;
            xa[pb][3] = 0u;
        }

        // ---- layer 1 as MMA: acc1[pb][nt 8][4] = X(16x16) x W1^T(64x16) ----
        float acc1[2][8][4];
        #pragma unroll
        for (int nt = 0; nt < 8; ++nt) {
            float2 bb = *reinterpret_cast<const float2*>(&s_c1[nt*8 + qc]);
            #pragma unroll
            for (int pb = 0; pb < 2; ++pb) {
                acc1[pb][nt][0] = bb.x; acc1[pb][nt][1] = bb.y;
                acc1[pb][nt][2] = bb.x; acc1[pb][nt][3] = bb.y;
            }
        }
        #pragma unroll
        for (int np = 0; np < 4; ++np) {
            u32 b[4];
            ldm4(b[0], b[1], b[2], b[3], w1base + np*(16*W1STRIDE*2));
            mma16816(acc1[0][2*np],   xa[0], b[0], b[2]);
            mma16816(acc1[0][2*np+1], xa[0], b[1], b[3]);
            mma16816(acc1[1][2*np],   xa[1], b[0], b[2]);
            mma16816(acc1[1][2*np+1], xa[1], b[1], b[3]);
        }

        // ---- relu+pack acc1 -> layer-2 A fragments (registers) ----
        u32 y1a[2][4][4];
        #pragma unroll
        for (int pb = 0; pb < 2; ++pb)
            #pragma unroll
            for (int kt = 0; kt < 4; ++kt) {
                y1a[pb][kt][0] = pack2(fmaxf(acc1[pb][2*kt][0],   0.f), fmaxf(acc1[pb][2*kt][1],   0.f));
                y1a[pb][kt][1] = pack2(fmaxf(acc1[pb][2*kt][2],   0.f), fmaxf(acc1[pb][2*kt][3],   0.f));
                y1a[pb][kt][2] = pack2(fmaxf(acc1[pb][2*kt+1][0], 0.f), fmaxf(acc1[pb][2*kt+1][1], 0.f));
                y1a[pb][kt][3] = pack2(fmaxf(acc1[pb][2*kt+1][2], 0.f), fmaxf(acc1[pb][2*kt+1][3], 0.f));
            }

        // ---- layer 2: acc2[pb 2][nt 8][4], A from registers ----
        float acc2[2][8][4];
        #pragma unroll
        for (int nt = 0; nt < 8; ++nt) {
            float2 bb = *reinterpret_cast<const float2*>(&s_c2[nt*8 + qc]);
            #pragma unroll
            for (int pb = 0; pb < 2; ++pb) {
                acc2[pb][nt][0] = bb.x; acc2[pb][nt][1] = bb.y;
                acc2[pb][nt][2] = bb.x; acc2[pb][nt][3] = bb.y;
            }
        }
        #pragma unroll
        for (int kt = 0; kt < 4; ++kt) {
            #pragma unroll
            for (int np = 0; np < 4; ++np) {
                u32 b[4];
                ldm4(b[0], b[1], b[2], b[3], w2base + np*(16*RSTRIDE*2) + kt*32);
                // x4 fill: b0=(nlo,klo) b1=(nhi,klo) b2=(nlo,khi) b3=(nhi,khi)
                mma16816(acc2[0][2*np],   y1a[0][kt], b[0], b[2]);
                mma16816(acc2[0][2*np+1], y1a[0][kt], b[1], b[3]);
                mma16816(acc2[1][2*np],   y1a[1][kt], b[0], b[2]);
                mma16816(acc2[1][2*np+1], y1a[1][kt], b[1], b[3]);
            }
        }

        // ---- relu+pack acc2 -> layer-3 B fragments (registers) ----
        u32 y2b[2][4][2][2];
        #pragma unroll
        for (int pb = 0; pb < 2; ++pb)
            #pragma unroll
            for (int kt = 0; kt < 4; ++kt) {
                y2b[pb][kt][0][0] = pack2(fmaxf(acc2[pb][2*kt][0],   0.f), fmaxf(acc2[pb][2*kt][1],   0.f));
                y2b[pb][kt][0][1] = pack2(fmaxf(acc2[pb][2*kt+1][0], 0.f), fmaxf(acc2[pb][2*kt+1][1], 0.f));
                y2b[pb][kt][1][0] = pack2(fmaxf(acc2[pb][2*kt][2],   0.f), fmaxf(acc2[pb][2*kt][3],   0.f));
                y2b[pb][kt][1][1] = pack2(fmaxf(acc2[pb][2*kt+1][2], 0.f), fmaxf(acc2[pb][2*kt+1][3], 0.f));
            }

        // ---- valid mask for epilogue columns via shuffle ----
        float2 vv[2][2];
        #pragma unroll
        for (int pb = 0; pb < 2; ++pb)
            #pragma unroll
            for (int h = 0; h < 2; ++h) {
                int src = pb*16 + h*8 + qc;
                vv[pb][h].x = __shfl_sync(0xffffffffu, vldc, src);
                vv[pb][h].y = __shfl_sync(0xffffffffu, vldc, src + 1);
            }

        // ---- layer 3: [out3 128][pos 32] per warp, streaming STG.128 ----
        {
            float* outb = out + (size_t)p0 + w*32;
            #pragma unroll
            for (int ob = 0; ob < 8; ++ob) {
                float bq0 = s_c3[ob*16 + qr];
                float bq8 = s_c3[ob*16 + qr + 8];
                float acc[2][2][4];
                #pragma unroll
                for (int pb = 0; pb < 2; ++pb)
                    #pragma unroll
                    for (int h = 0; h < 2; ++h) {
                        acc[pb][h][0] = bq0; acc[pb][h][1] = bq0;
                        acc[pb][h][2] = bq8; acc[pb][h][3] = bq8;
                    }
                #pragma unroll
                for (int kt = 0; kt < 4; ++kt) {
                    u32 a[4];
                    ldm4(a[0], a[1], a[2], a[3], w3base + ob*(16*RSTRIDE*2) + kt*32);
                    mma16816(acc[0][0], a, y2b[0][kt][0][0], y2b[0][kt][0][1]);
                    mma16816(acc[0][1], a, y2b[0][kt][1][0], y2b[0][kt][1][1]);
                    mma16816(acc[1][0], a, y2b[1][kt][0][0], y2b[1][kt][0][1]);
                    mma16816(acc[1][1], a, y2b[1][kt][1][0], y2b[1][kt][1][1]);
                }
                const int c0i = ob*16 + qr;
                #pragma unroll
                for (int pb = 0; pb < 2; ++pb) {
                    float r0 = fmaxf(acc[pb][0][0], 0.f) * vv[pb][0].x;
                    float r1 = fmaxf(acc[pb][0][1], 0.f) * vv[pb][0].y;
                    float r2 = fmaxf(acc[pb][0][2], 0.f) * vv[pb][0].x;
                    float r3 = fmaxf(acc[pb][0][3], 0.f) * vv[pb][0].y;
                    float s0 = fmaxf(acc[pb][1][0], 0.f) * vv[pb][1].x;
                    float s1 = fmaxf(acc[pb][1][1], 0.f) * vv[pb][1].y;
                    float s2 = fmaxf(acc[pb][1][2], 0.f) * vv[pb][1].x;
                    float s3 = fmaxf(acc[pb][1][3], 0.f) * vv[pb][1].y;
                    float m0 = oddq ? r0 : s0;
                    float m1 = oddq ? r1 : s1;
                    float m2 = oddq ? r2 : s2;
                    float m3 = oddq ? r3 : s3;
                    float g0  = __shfl_xor_sync(0xffffffffu, m0, 1);
                    float g1v = __shfl_xor_sync(0xffffffffu, m1, 1);
                    float g2v = __shfl_xor_sync(0xffffffffu, m2, 1);
                    float g3v = __shfl_xor_sync(0xffffffffu, m3, 1);
                    float4 t0, t1;
                    t0.x = oddq ? g0  : r0;  t0.y = oddq ? g1v : r1;
                    t0.z = oddq ? s0  : g0;  t0.w = oddq ? s1  : g1v;
                    t1.x = oddq ? g2v : r2;  t1.y = oddq ? g3v : r3;
                    t1.z = oddq ? s2  : g2v; t1.w = oddq ? s3  : g3v;
                    const int colb = pb*16 + colq;
                    __stcs(reinterpret_cast<float4*>(outb + (size_t)c0i*NPOS + colb),     t0);
                    __stcs(reinterpret_cast<float4*>(outb + (size_t)(c0i+8)*NPOS + colb), t1);
                }
            }
        }
    }
}

extern "C" void kernel_launch(void* const* d_in, const int* in_sizes, int n_in,
                              void* d_out, int out_size)
{
    (void)in_sizes; (void)n_in; (void)out_size;
    cudaFuncSetAttribute(pn_mma_kernel,
                         cudaFuncAttributeMaxDynamicSharedMemorySize, SMEM_TOTAL);
    pn_mma_kernel<<<NBLOCKS, THREADS, SMEM_TOTAL>>>(
        (const float*)d_in[0],  (const float*)d_in[1],
        (const float*)d_in[2],  (const float*)d_in[3],  (const float*)d_in[4],
        (const float*)d_in[5],  (const float*)d_in[6],  (const float*)d_in[7],
        (const float*)d_in[8],  (const float*)d_in[9],  (const float*)d_in[10],
        (const float*)d_in[11], (const float*)d_in[12], (const float*)d_in[13],
        (const float*)d_in[14], (const float*)d_in[15], (const float*)d_in[16],
        (const float*)d_in[17], (const float*)d_in[18], (const float*)d_in[19],
        (float*)d_out);
}